// round 1
// baseline (speedup 1.0000x reference)
#include <cuda_runtime.h>

#define FULL 0xffffffffu

// 16 gates (2 layers x 8 qubits), 8 floats each:
// u00r,u00i,u01r,u01i,u10r,u10i,u11r,u11i
__device__ float g_gates[16 * 8];

__global__ void precompute_gates_kernel(const float* __restrict__ theta) {
    int g = threadIdx.x;
    if (g >= 16) return;
    float phi = theta[g * 3 + 0];
    float th  = theta[g * 3 + 1];
    float om  = theta[g * 3 + 2];
    float st, ct;
    sincosf(0.5f * th, &st, &ct);
    float a = 0.5f * (phi + om);
    float b = 0.5f * (phi - om);
    float sa, ca, sb, cb;
    sincosf(a, &sa, &ca);
    sincosf(b, &sb, &cb);
    float* o = &g_gates[g * 8];
    // u00 = e^{-ia} ct
    o[0] =  ca * ct; o[1] = -sa * ct;
    // u01 = -e^{+ib} st
    o[2] = -cb * st; o[3] = -sb * st;
    // u10 = e^{-ib} st
    o[4] =  cb * st; o[5] = -sb * st;
    // u11 = e^{+ia} ct
    o[6] =  ca * ct; o[7] =  sa * ct;
}

__global__ void __launch_bounds__(256)
qsim_kernel(const float* __restrict__ x, float* __restrict__ out, int batch) {
    int warp = (int)((blockIdx.x * blockDim.x + threadIdx.x) >> 5);
    int lane = threadIdx.x & 31;
    if (warp >= batch) return;

    // ---- angle encoding as a product state ----
    float xv = x[warp * 8 + (lane & 7)];
    xv = fminf(1.0f, fmaxf(-1.0f, xv));
    float s, c;
    sincospif(0.5f * xv, &s, &c);   // sin/cos(0.5*pi*x)

    // lane factor: qubits 3..7 live in lane bits 0..4
    float lf = 1.0f;
    #pragma unroll
    for (int q = 3; q < 8; q++) {
        float cq = __shfl_sync(FULL, c, q);
        float sq = __shfl_sync(FULL, s, q);
        lf *= (((lane >> (q - 3)) & 1) ? sq : cq);
    }
    float c0 = __shfl_sync(FULL, c, 0), s0 = __shfl_sync(FULL, s, 0);
    float c1 = __shfl_sync(FULL, c, 1), s1 = __shfl_sync(FULL, s, 1);
    float c2 = __shfl_sync(FULL, c, 2), s2 = __shfl_sync(FULL, s, 2);

    float ar[8], ai[8];
    #pragma unroll
    for (int j = 0; j < 8; j++) {
        ar[j] = lf * ((j & 1) ? s0 : c0) * ((j & 2) ? s1 : c1) * ((j & 4) ? s2 : c2);
        ai[j] = 0.0f;
    }

    // ---- variational layers ----
    #pragma unroll
    for (int layer = 0; layer < 2; layer++) {
        #pragma unroll
        for (int q = 0; q < 8; q++) {
            const float* g = &g_gates[(layer * 8 + q) * 8];
            float u00r = g[0], u00i = g[1], u01r = g[2], u01i = g[3];
            float u10r = g[4], u10i = g[5], u11r = g[6], u11i = g[7];
            if (q < 3) {
                // in-lane pairs
                int m = 1 << q;
                #pragma unroll
                for (int j0 = 0; j0 < 8; j0++) {
                    if (j0 & m) continue;
                    int j1 = j0 | m;
                    float a0r = ar[j0], a0i = ai[j0];
                    float a1r = ar[j1], a1i = ai[j1];
                    ar[j0] = u00r * a0r - u00i * a0i + u01r * a1r - u01i * a1i;
                    ai[j0] = u00r * a0i + u00i * a0r + u01r * a1i + u01i * a1r;
                    ar[j1] = u10r * a0r - u10i * a0i + u11r * a1r - u11i * a1i;
                    ai[j1] = u10r * a0i + u10i * a0r + u11r * a1i + u11i * a1r;
                }
            } else {
                // cross-lane pairs via shfl_xor
                int pb = 1 << (q - 3);
                bool hi = ((lane >> (q - 3)) & 1) != 0;
                float v0r = hi ? u10r : u00r, v0i = hi ? u10i : u00i;
                float v1r = hi ? u11r : u01r, v1i = hi ? u11i : u01i;
                #pragma unroll
                for (int j = 0; j < 8; j++) {
                    float pr = __shfl_xor_sync(FULL, ar[j], pb);
                    float pi = __shfl_xor_sync(FULL, ai[j], pb);
                    float a0r = hi ? pr : ar[j], a0i = hi ? pi : ai[j];
                    float a1r = hi ? ar[j] : pr, a1i = hi ? ai[j] : pi;
                    ar[j] = v0r * a0r - v0i * a0i + v1r * a1r - v1i * a1i;
                    ai[j] = v0r * a0i + v0i * a0r + v1r * a1i + v1i * a1r;
                }
            }
        }

        // ---- CNOT chain (c, c+1), c = 0..6 ----
        // (0,1): local bit0 -> flip bit1: swap 1<->3, 5<->7
        {
            float t;
            t = ar[1]; ar[1] = ar[3]; ar[3] = t;
            t = ai[1]; ai[1] = ai[3]; ai[3] = t;
            t = ar[5]; ar[5] = ar[7]; ar[7] = t;
            t = ai[5]; ai[5] = ai[7]; ai[7] = t;
        }
        // (1,2): local bit1 -> flip bit2: swap 2<->6, 3<->7
        {
            float t;
            t = ar[2]; ar[2] = ar[6]; ar[6] = t;
            t = ai[2]; ai[2] = ai[6]; ai[6] = t;
            t = ar[3]; ar[3] = ar[7]; ar[7] = t;
            t = ai[3]; ai[3] = ai[7]; ai[7] = t;
        }
        // (2,3): control = local bit2 (j>=4), target = lane bit0:
        // swap j=4..7 amplitudes between lane and lane^1
        #pragma unroll
        for (int j = 4; j < 8; j++) {
            ar[j] = __shfl_xor_sync(FULL, ar[j], 1);
            ai[j] = __shfl_xor_sync(FULL, ai[j], 1);
        }
        // (c, c+1) for c = 3..6: both lane bits
        #pragma unroll
        for (int cq = 3; cq < 7; cq++) {
            int cb = 1 << (cq - 3);
            int tb = 1 << (cq - 2);
            bool ctl = (lane & cb) != 0;
            #pragma unroll
            for (int j = 0; j < 8; j++) {
                float pr = __shfl_xor_sync(FULL, ar[j], tb);
                float pi = __shfl_xor_sync(FULL, ai[j], tb);
                if (ctl) { ar[j] = pr; ai[j] = pi; }
            }
        }
    }

    // ---- expectation <Z_q> ----
    float p[8];
    float S = 0.0f;
    #pragma unroll
    for (int j = 0; j < 8; j++) {
        p[j] = ar[j] * ar[j] + ai[j] * ai[j];
        S += p[j];
    }
    float e[8];
    e[0] = (p[0] - p[1]) + (p[2] - p[3]) + (p[4] - p[5]) + (p[6] - p[7]);
    e[1] = (p[0] + p[1]) - (p[2] + p[3]) + (p[4] + p[5]) - (p[6] + p[7]);
    e[2] = (p[0] + p[1] + p[2] + p[3]) - (p[4] + p[5] + p[6] + p[7]);
    #pragma unroll
    for (int q = 3; q < 8; q++)
        e[q] = (((lane >> (q - 3)) & 1) ? -S : S);

    // butterfly sum over the 32 lanes for all 8 outputs
    #pragma unroll
    for (int d = 1; d < 32; d <<= 1) {
        #pragma unroll
        for (int q = 0; q < 8; q++)
            e[q] += __shfl_xor_sync(FULL, e[q], d);
    }

    if (lane == 0) {
        #pragma unroll
        for (int q = 0; q < 8; q++)
            out[warp * 8 + q] = e[q];
    }
}

extern "C" void kernel_launch(void* const* d_in, const int* in_sizes, int n_in,
                              void* d_out, int out_size) {
    const float* inputs = (const float*)d_in[0];   // [16384, 8] f32
    const float* theta  = (const float*)d_in[1];   // [2, 8, 3]  f32
    float* out = (float*)d_out;                    // [16384, 8] f32

    int batch = in_sizes[0] / 8;

    precompute_gates_kernel<<<1, 16>>>(theta);

    int threads = 256;                       // 8 warps = 8 samples / block
    int blocks = (batch * 32 + threads - 1) / threads;
    qsim_kernel<<<blocks, threads>>>(inputs, out, batch);
}

// round 2
// speedup vs baseline: 1.3969x; 1.3969x over previous
#include <cuda_runtime.h>

#define FULL 0xffffffffu

// 16 gates (2 layers x 8 qubits), 8 floats each:
// u00r,u00i,u01r,u01i,u10r,u10i,u11r,u11i
__device__ float g_gates[16 * 8];

__global__ void precompute_gates_kernel(const float* __restrict__ theta) {
    int g = threadIdx.x;
    if (g >= 16) return;
    float phi = theta[g * 3 + 0];
    float th  = theta[g * 3 + 1];
    float om  = theta[g * 3 + 2];
    float st, ct;
    sincosf(0.5f * th, &st, &ct);
    float a = 0.5f * (phi + om);
    float b = 0.5f * (phi - om);
    float sa, ca, sb, cb;
    sincosf(a, &sa, &ca);
    sincosf(b, &sb, &cb);
    float* o = &g_gates[g * 8];
    o[0] =  ca * ct; o[1] = -sa * ct;   // u00 = e^{-ia} ct
    o[2] = -cb * st; o[3] = -sb * st;   // u01 = -e^{+ib} st
    o[4] =  cb * st; o[5] = -sb * st;   // u10 = e^{-ib} st
    o[6] =  ca * ct; o[7] =  sa * ct;   // u11 = e^{+ia} ct
}

__global__ void __launch_bounds__(256)
qsim_kernel(const float* __restrict__ x, float* __restrict__ out, int batch) {
    int warp = (int)((blockIdx.x * blockDim.x + threadIdx.x) >> 5);
    int lane = threadIdx.x & 31;
    if (warp >= batch) return;

    // ---- angle encoding as a product state ----
    float xv = x[warp * 8 + (lane & 7)];
    xv = fminf(1.0f, fmaxf(-1.0f, xv));
    float s, c;
    sincospif(0.5f * xv, &s, &c);   // sin/cos(0.5*pi*x)

    // lane factor: qubits 3..7 live in lane bits 0..4
    float lf = 1.0f;
    #pragma unroll
    for (int q = 3; q < 8; q++) {
        float cq = __shfl_sync(FULL, c, q);
        float sq = __shfl_sync(FULL, s, q);
        lf *= (((lane >> (q - 3)) & 1) ? sq : cq);
    }
    float c0 = __shfl_sync(FULL, c, 0), s0 = __shfl_sync(FULL, s, 0);
    float c1 = __shfl_sync(FULL, c, 1), s1 = __shfl_sync(FULL, s, 1);
    float c2 = __shfl_sync(FULL, c, 2), s2 = __shfl_sync(FULL, s, 2);

    float ar[8], ai[8];
    #pragma unroll
    for (int j = 0; j < 8; j++) {
        ar[j] = lf * ((j & 1) ? s0 : c0) * ((j & 2) ? s1 : c1) * ((j & 4) ? s2 : c2);
        ai[j] = 0.0f;
    }

    // Precompute CNOT-chain permutation source lanes (used after layer 0 only)
    const int sl0 = lane ^ ((lane & 15) << 1);
    const int sl1 = sl0 ^ 1;

    // ---- variational layers ----
    #pragma unroll
    for (int layer = 0; layer < 2; layer++) {
        #pragma unroll
        for (int q = 0; q < 8; q++) {
            const float4* g4 = reinterpret_cast<const float4*>(&g_gates[(layer * 8 + q) * 8]);
            float4 gA = g4[0];   // u00r,u00i,u01r,u01i
            float4 gB = g4[1];   // u10r,u10i,u11r,u11i
            if (q < 3) {
                // in-lane pairs
                int m = 1 << q;
                #pragma unroll
                for (int j0 = 0; j0 < 8; j0++) {
                    if (j0 & m) continue;
                    int j1 = j0 | m;
                    float a0r = ar[j0], a0i = ai[j0];
                    float a1r = ar[j1], a1i = ai[j1];
                    ar[j0] = gA.x * a0r - gA.y * a0i + gA.z * a1r - gA.w * a1i;
                    ai[j0] = gA.x * a0i + gA.y * a0r + gA.z * a1i + gA.w * a1r;
                    ar[j1] = gB.x * a0r - gB.y * a0i + gB.z * a1r - gB.w * a1i;
                    ai[j1] = gB.x * a0i + gB.y * a0r + gB.z * a1i + gB.w * a1r;
                }
            } else {
                // cross-lane pairs: select COEFFICIENTS once, no per-j data selects.
                // lo lane: new = u00*self + u01*partner
                // hi lane: new = u11*self + u10*partner
                int pb = 1 << (q - 3);
                bool hi = (lane & pb) != 0;
                float vsr = hi ? gB.z : gA.x, vsi = hi ? gB.w : gA.y;
                float vpr = hi ? gB.x : gA.z, vpi = hi ? gB.y : gA.w;
                #pragma unroll
                for (int j = 0; j < 8; j++) {
                    float pr = __shfl_xor_sync(FULL, ar[j], pb);
                    float pi = __shfl_xor_sync(FULL, ai[j], pb);
                    float nr = vsr * ar[j] - vsi * ai[j] + vpr * pr - vpi * pi;
                    float ni = vsr * ai[j] + vsi * ar[j] + vpr * pi + vpi * pr;
                    ar[j] = nr; ai[j] = ni;
                }
            }
        }

        if (layer == 0) {
            // ---- full CNOT chain as ONE lane/reg permutation ----
            // src_index = I ^ ((I & 0x7F) << 1); dest reg j <- src reg j^((j&3)<<1),
            // src lane = sl0 ^ (j>>2).
            float br[8], bi[8];
            br[0] = __shfl_sync(FULL, ar[0], sl0);  bi[0] = __shfl_sync(FULL, ai[0], sl0);
            br[1] = __shfl_sync(FULL, ar[3], sl0);  bi[1] = __shfl_sync(FULL, ai[3], sl0);
            br[2] = __shfl_sync(FULL, ar[6], sl0);  bi[2] = __shfl_sync(FULL, ai[6], sl0);
            br[3] = __shfl_sync(FULL, ar[5], sl0);  bi[3] = __shfl_sync(FULL, ai[5], sl0);
            br[4] = __shfl_sync(FULL, ar[4], sl1);  bi[4] = __shfl_sync(FULL, ai[4], sl1);
            br[5] = __shfl_sync(FULL, ar[7], sl1);  bi[5] = __shfl_sync(FULL, ai[7], sl1);
            br[6] = __shfl_sync(FULL, ar[2], sl1);  bi[6] = __shfl_sync(FULL, ai[2], sl1);
            br[7] = __shfl_sync(FULL, ar[1], sl1);  bi[7] = __shfl_sync(FULL, ai[1], sl1);
            #pragma unroll
            for (int j = 0; j < 8; j++) { ar[j] = br[j]; ai[j] = bi[j]; }
        }
        // layer 1's CNOT chain is folded into the measurement (Walsh masks below)
    }

    // ---- measurement: <Z_q> after the (skipped) final CNOT chain ----
    // <Z_q> = sum_J (-1)^{parity(J & (2^{q+1}-1))} p[J]
    float p[8];
    #pragma unroll
    for (int j = 0; j < 8; j++)
        p[j] = ar[j] * ar[j] + ai[j] * ai[j];

    // local (in-reg) signed combos over bits 0..2:
    float a = (p[0] - p[1]) + (p[2] - p[3]) + (p[4] - p[5]) + (p[6] - p[7]);       // parity(j&1)
    float b = (p[0] - p[1]) - (p[2] - p[3]) + (p[4] - p[5]) - (p[6] - p[7]);       // parity(j&3)
    float cc = (p[0] - p[1]) - (p[2] - p[3]) - (p[4] - p[5]) + (p[6] - p[7]);      // parity(j&7)

    // e0,e1: plain lane sums of a,b
    #pragma unroll
    for (int d = 1; d < 32; d <<= 1) {
        a += __shfl_xor_sync(FULL, a, d);
        b += __shfl_xor_sync(FULL, b, d);
    }
    // e2..e7: fast Walsh transform of cc over lanes; lane m holds
    // sum_L (-1)^{popc(L&m)} cc_L. Needed masks: 0,1,3,7,15,31.
    #pragma unroll
    for (int d = 1; d < 32; d <<= 1) {
        float pv = __shfl_xor_sync(FULL, cc, d);
        cc = (lane & d) ? (pv - cc) : (cc + pv);
    }

    float* o = out + warp * 8;
    if (lane == 0) {
        o[0] = a;
        o[1] = b;
        o[2] = cc;          // mask 0 (plain sum)
    } else if ((lane & (lane + 1)) == 0) {
        // lanes 1,3,7,15,31 -> qubits 3..7
        o[2 + __popc(lane)] = cc;
    }
}

extern "C" void kernel_launch(void* const* d_in, const int* in_sizes, int n_in,
                              void* d_out, int out_size) {
    const float* inputs = (const float*)d_in[0];   // [16384, 8] f32
    const float* theta  = (const float*)d_in[1];   // [2, 8, 3]  f32
    float* out = (float*)d_out;                    // [16384, 8] f32

    int batch = in_sizes[0] / 8;

    precompute_gates_kernel<<<1, 16>>>(theta);

    int threads = 256;                       // 8 warps = 8 samples / block
    int blocks = (batch * 32 + threads - 1) / threads;
    qsim_kernel<<<blocks, threads>>>(inputs, out, batch);
}